// round 3
// baseline (speedup 1.0000x reference)
#include <cuda_runtime.h>
#include <cstdint>

// ---------------------------------------------------------------------------
// HyperTransposeConv: 8-component hypercomplex ConvTranspose2d
//   x[8,512,64,64] fp32, W[8,64,32,4,4], b[8,32] -> out[8,256,128,128]
//   stride=2, padding=1, K=4, output_padding=0
//
// Decomposition: stride-2 transpose conv == 4 parity classes (py,px), each a
// 2x2-tap stride-1 conv on the 64x64 grid:
//   out[b,co,2y+py,2x+px] = sum_{dy,dx in {0,1}} sum_ci
//        x[b,ci, y+py-dy, x+px-dx] * Wbig[ci,co, 2dy+1-py, 2dx+1-px]
// (input coords outside [0,64) contribute 0)
// ---------------------------------------------------------------------------

#define NCOMP 8
#define CIN   512
#define COUT  256
#define HIN   64
#define HOUT  128
#define BATCH 8

// Cayley-Dickson component table, get_comp_mat(8), row-major [i][j]
__device__ const int COMP[64] = {
    0,-1,-2,-1,-4,-3,-2,-3,
    1, 0,-3,-2,-5,-4,-1,-2,
    2, 1, 0,-1,-6,-5,-4,-3,
    3, 2, 1, 0,-7,-6,-5,-4,
    4, 3, 2, 3, 0,-1,-2,-1,
    5, 4, 1, 2, 1, 0,-3,-2,
    6, 5, 4, 3, 2, 1, 0,-1,
    7, 6, 5, 4, 3, 2, 1, 0};

// Scratch: fused weights per (parity, tap): [4][4][512][256]  (8 MB)
__device__ float g_Wpar[4 * 4 * CIN * COUT];
__device__ float g_bias[COUT];

// ---------------------------------------------------------------------------
// Prep: Wpar[par][tap][ci_g][co_g] = sign[i][j] * W[idx[i][j]][cj][co'][ky][kx]
//   ci_g = j*64+cj, co_g = i*32+co', ky = 2*dy+1-py, kx = 2*dx+1-px
// ---------------------------------------------------------------------------
__global__ void prep_w_kernel(const float* __restrict__ W)
{
    int idx = blockIdx.x * blockDim.x + threadIdx.x;
    if (idx >= 4 * 4 * CIN * COUT) return;
    int co_g = idx & 255;
    int ci_g = (idx >> 8) & 511;
    int tap  = (idx >> 17) & 3;
    int par  = idx >> 19;

    int i   = co_g >> 5, cop = co_g & 31;
    int j   = ci_g >> 6, cj  = ci_g & 63;
    int c   = COMP[i * 8 + j];
    float sign = (c < 0) ? -1.0f : 1.0f;
    int widx = (c < 0) ? -c : c;

    int py = par >> 1, px = par & 1;
    int dy = tap >> 1, dx = tap & 1;
    int ky = 2 * dy + 1 - py;
    int kx = 2 * dx + 1 - px;

    g_Wpar[idx] = sign * W[(((widx * 64 + cj) * 32 + cop) * 4 + ky) * 4 + kx];
}

__global__ void prep_b_kernel(const float* __restrict__ b)
{
    int co_g = threadIdx.x;            // 256 threads
    int i = co_g >> 5, cop = co_g & 31;
    float s = 0.0f;
    #pragma unroll
    for (int j = 0; j < 8; j++) {
        int c = COMP[i * 8 + j];
        float sign = (c < 0) ? -1.0f : 1.0f;
        int widx = (c < 0) ? -c : c;
        s += sign * b[widx * 32 + cop];
    }
    g_bias[co_g] = s;
}

// ---------------------------------------------------------------------------
// Main conv kernel.
// Grid: (32 pixel tiles [16 ytiles x 2 xtiles], 2 co tiles, 32 = b*4+parity)
// Block: 256 threads. Per block: 128 co x (4 rows x 32 cols) pixels.
// Thread (tc=tid>>4, tp=tid&15): 8 co (pairs) x 8 px, row tr=tp>>2, colgrp cg=tp&3.
// Accumulate with packed fma.rn.f32x2: co pairs packed (w pairs loaded as b64
// straight from smem), x broadcast-packed once per scalar.
// ---------------------------------------------------------------------------
#define KC 8          // ci per chunk
#define TY 4
#define TX 32
#define XPAD 37       // row stride (conflict-free for this access pattern)

__device__ __forceinline__ unsigned long long dup_f32(float v)
{
    unsigned long long d;
    unsigned r = __float_as_uint(v);
    asm("mov.b64 %0, {%1, %1};" : "=l"(d) : "r"(r));
    return d;
}

__global__ void __launch_bounds__(256, 1)
hconv_kernel(const float* __restrict__ x, float* __restrict__ out)
{
    __shared__ __align__(16) float Xs[KC][TY + 1][XPAD];
    __shared__ __align__(16) float Ws[KC][4][128];

    const int tid = threadIdx.x;
    const int y0  = (blockIdx.x >> 1) * TY;
    const int x0  = (blockIdx.x & 1) * TX;
    const int co0 = blockIdx.y * 128;
    const int z   = blockIdx.z;
    const int b   = z >> 2;
    const int par = z & 3;
    const int py  = par >> 1;
    const int px  = par & 1;

    const int tc = tid >> 4;          // 0..15  -> co block of 8
    const int tp = tid & 15;
    const int tr = tp >> 2;           // 0..3   pixel row
    const int cg = tp & 3;            // 0..3   pixel col group
    const int c0 = cg * 8;

    const float* xb = x + (size_t)b * CIN * HIN * HIN;

    unsigned long long acc2[4][8];
    #pragma unroll
    for (int cp = 0; cp < 4; cp++)
        #pragma unroll
        for (int j = 0; j < 8; j++) acc2[cp][j] = 0ull;

    for (int cc = 0; cc < CIN; cc += KC) {
        // ---- load X tile: KC x (TY+1) x (TX+1) with zero halo ----
        for (int idx = tid; idx < KC * 5 * 33; idx += 256) {
            int ci = idx / 165;
            int r  = idx - ci * 165;
            int ry = r / 33;
            int rx = r - ry * 33;
            int iy = y0 + py - 1 + ry;
            int ix = x0 + px - 1 + rx;
            float v = 0.0f;
            if ((unsigned)iy < (unsigned)HIN && (unsigned)ix < (unsigned)HIN)
                v = xb[(cc + ci) * (HIN * HIN) + iy * HIN + ix];
            Xs[ci][ry][rx] = v;
        }
        // ---- load W tile: KC x 4taps x 128co ----
        for (int idx = tid; idx < KC * 4 * 128; idx += 256) {
            int ci  = idx >> 9;
            int tap = (idx >> 7) & 3;
            int co  = idx & 127;
            Ws[ci][tap][co] =
                g_Wpar[((size_t)(par * 4 + tap) * CIN + cc + ci) * COUT + co0 + co];
        }
        __syncthreads();

        #pragma unroll
        for (int ci = 0; ci < KC; ci++) {
            // broadcast-packed x window: rows tr,tr+1, cols [c0, c0+9)
            unsigned long long xd[2][9];
            #pragma unroll
            for (int s = 0; s < 2; s++)
                #pragma unroll
                for (int e = 0; e < 9; e++)
                    xd[s][e] = dup_f32(Xs[ci][tr + s][c0 + e]);

            #pragma unroll
            for (int t = 0; t < 4; t++) {
                const int dy = t >> 1, dx = t & 1;
                const unsigned long long* wrow =
                    reinterpret_cast<const unsigned long long*>(&Ws[ci][t][0]);
                unsigned long long wp4[4];
                #pragma unroll
                for (int cp = 0; cp < 4; cp++) wp4[cp] = wrow[tc * 4 + cp];
                #pragma unroll
                for (int cp = 0; cp < 4; cp++)
                    #pragma unroll
                    for (int j = 0; j < 8; j++)
                        asm("fma.rn.f32x2 %0, %1, %2, %0;"
                            : "+l"(acc2[cp][j])
                            : "l"(wp4[cp]), "l"(xd[1 - dy][j + 1 - dx]));
            }
        }
        __syncthreads();
    }

    // ---- epilogue: unpack, add bias, write strided output ----
    const int oy = 2 * (y0 + tr) + py;
    #pragma unroll
    for (int cp = 0; cp < 4; cp++) {
        int co = co0 + tc * 8 + cp * 2;
        float b0 = __ldg(&g_bias[co]);
        float b1 = __ldg(&g_bias[co + 1]);
        float* o0 = out + ((size_t)(b * COUT + co) * HOUT + oy) * HOUT;
        float* o1 = o0 + (size_t)HOUT * HOUT;
        #pragma unroll
        for (int j = 0; j < 8; j++) {
            unsigned lo = (unsigned)(acc2[cp][j] & 0xffffffffull);
            unsigned hi = (unsigned)(acc2[cp][j] >> 32);
            int ox = 2 * (x0 + c0 + j) + px;
            o0[ox] = __uint_as_float(lo) + b0;
            o1[ox] = __uint_as_float(hi) + b1;
        }
    }
}

// ---------------------------------------------------------------------------
extern "C" void kernel_launch(void* const* d_in, const int* in_sizes, int n_in,
                              void* d_out, int out_size)
{
    const float* x = (const float*)d_in[0];   // [8,512,64,64]
    const float* W = (const float*)d_in[1];   // [8,64,32,4,4]
    const float* b = (const float*)d_in[2];   // [8,32]
    float* out = (float*)d_out;               // [8,256,128,128]

    prep_w_kernel<<<(4 * 4 * CIN * COUT + 255) / 256, 256>>>(W);
    prep_b_kernel<<<1, 256>>>(b);

    dim3 grid(32, 2, 32);
    hconv_kernel<<<grid, 256>>>(x, out);
}

// round 4
// speedup vs baseline: 1.0012x; 1.0012x over previous
#include <cuda_runtime.h>
#include <cstdint>

// ---------------------------------------------------------------------------
// HyperTransposeConv: 8-component hypercomplex ConvTranspose2d
//   x[8,512,64,64] fp32, W[8,64,32,4,4], b[8,32] -> out[8,256,128,128]
//   stride=2, padding=1, K=4, output_padding=0
//
// Decomposition: stride-2 transpose conv == 4 parity classes (py,px), each a
// 2x2-tap stride-1 conv on the 64x64 grid:
//   out[b,co,2y+py,2x+px] = sum_{dy,dx in {0,1}} sum_ci
//        x[b,ci, y+py-dy, x+px-dx] * Wbig[ci,co, 2dy+1-py, 2dx+1-px]
// (input coords outside [0,64) contribute 0)
// ---------------------------------------------------------------------------

#define NCOMP 8
#define CIN   512
#define COUT  256
#define HIN   64
#define HOUT  128
#define BATCH 8

// Cayley-Dickson component table, get_comp_mat(8), row-major [i][j]
__device__ const int COMP[64] = {
    0,-1,-2,-1,-4,-3,-2,-3,
    1, 0,-3,-2,-5,-4,-1,-2,
    2, 1, 0,-1,-6,-5,-4,-3,
    3, 2, 1, 0,-7,-6,-5,-4,
    4, 3, 2, 3, 0,-1,-2,-1,
    5, 4, 1, 2, 1, 0,-3,-2,
    6, 5, 4, 3, 2, 1, 0,-1,
    7, 6, 5, 4, 3, 2, 1, 0};

// Scratch: fused weights per (parity, tap): [4][4][512][256]  (8 MB)
__device__ float g_Wpar[4 * 4 * CIN * COUT];
__device__ float g_bias[COUT];

// ---------------------------------------------------------------------------
// Prep: Wpar[par][tap][ci_g][co_g] = sign[i][j] * W[idx[i][j]][cj][co'][ky][kx]
//   ci_g = j*64+cj, co_g = i*32+co', ky = 2*dy+1-py, kx = 2*dx+1-px
// ---------------------------------------------------------------------------
__global__ void prep_w_kernel(const float* __restrict__ W)
{
    int idx = blockIdx.x * blockDim.x + threadIdx.x;
    if (idx >= 4 * 4 * CIN * COUT) return;
    int co_g = idx & 255;
    int ci_g = (idx >> 8) & 511;
    int tap  = (idx >> 17) & 3;
    int par  = idx >> 19;

    int i   = co_g >> 5, cop = co_g & 31;
    int j   = ci_g >> 6, cj  = ci_g & 63;
    int c   = COMP[i * 8 + j];
    float sign = (c < 0) ? -1.0f : 1.0f;
    int widx = (c < 0) ? -c : c;

    int py = par >> 1, px = par & 1;
    int dy = tap >> 1, dx = tap & 1;
    int ky = 2 * dy + 1 - py;
    int kx = 2 * dx + 1 - px;

    g_Wpar[idx] = sign * W[(((widx * 64 + cj) * 32 + cop) * 4 + ky) * 4 + kx];
}

__global__ void prep_b_kernel(const float* __restrict__ b)
{
    int co_g = threadIdx.x;            // 256 threads
    int i = co_g >> 5, cop = co_g & 31;
    float s = 0.0f;
    #pragma unroll
    for (int j = 0; j < 8; j++) {
        int c = COMP[i * 8 + j];
        float sign = (c < 0) ? -1.0f : 1.0f;
        int widx = (c < 0) ? -c : c;
        s += sign * b[widx * 32 + cop];
    }
    g_bias[co_g] = s;
}

// ---------------------------------------------------------------------------
// Main conv kernel.
// Grid: (32 pixel tiles [16 ytiles x 2 xtiles], 2 co tiles, 32 = b*4+parity)
// Block: 256 threads. Per block: 128 co x (4 rows x 32 cols) pixels.
// Thread (tc=tid>>4, tp=tid&15): 8 co (pairs) x 8 px, row tr=tp>>2, colgrp cg=tp&3.
// Accumulate with packed fma.rn.f32x2: co pairs packed (w pairs loaded as b64
// straight from smem), x broadcast-packed once per scalar.
// ---------------------------------------------------------------------------
#define KC 8          // ci per chunk
#define TY 4
#define TX 32
#define XPAD 37       // row stride (conflict-free for this access pattern)

__device__ __forceinline__ unsigned long long dup_f32(float v)
{
    unsigned long long d;
    unsigned r = __float_as_uint(v);
    asm("mov.b64 %0, {%1, %1};" : "=l"(d) : "r"(r));
    return d;
}

__global__ void __launch_bounds__(256, 1)
hconv_kernel(const float* __restrict__ x, float* __restrict__ out)
{
    __shared__ __align__(16) float Xs[KC][TY + 1][XPAD];
    __shared__ __align__(16) float Ws[KC][4][128];

    const int tid = threadIdx.x;
    const int y0  = (blockIdx.x >> 1) * TY;
    const int x0  = (blockIdx.x & 1) * TX;
    const int co0 = blockIdx.y * 128;
    const int z   = blockIdx.z;
    const int b   = z >> 2;
    const int par = z & 3;
    const int py  = par >> 1;
    const int px  = par & 1;

    const int tc = tid >> 4;          // 0..15  -> co block of 8
    const int tp = tid & 15;
    const int tr = tp >> 2;           // 0..3   pixel row
    const int cg = tp & 3;            // 0..3   pixel col group
    const int c0 = cg * 8;

    const float* xb = x + (size_t)b * CIN * HIN * HIN;

    unsigned long long acc2[4][8];
    #pragma unroll
    for (int cp = 0; cp < 4; cp++)
        #pragma unroll
        for (int j = 0; j < 8; j++) acc2[cp][j] = 0ull;

    for (int cc = 0; cc < CIN; cc += KC) {
        // ---- load X tile: KC x (TY+1) x (TX+1) with zero halo ----
        for (int idx = tid; idx < KC * 5 * 33; idx += 256) {
            int ci = idx / 165;
            int r  = idx - ci * 165;
            int ry = r / 33;
            int rx = r - ry * 33;
            int iy = y0 + py - 1 + ry;
            int ix = x0 + px - 1 + rx;
            float v = 0.0f;
            if ((unsigned)iy < (unsigned)HIN && (unsigned)ix < (unsigned)HIN)
                v = xb[(cc + ci) * (HIN * HIN) + iy * HIN + ix];
            Xs[ci][ry][rx] = v;
        }
        // ---- load W tile: KC x 4taps x 128co ----
        for (int idx = tid; idx < KC * 4 * 128; idx += 256) {
            int ci  = idx >> 9;
            int tap = (idx >> 7) & 3;
            int co  = idx & 127;
            Ws[ci][tap][co] =
                g_Wpar[((size_t)(par * 4 + tap) * CIN + cc + ci) * COUT + co0 + co];
        }
        __syncthreads();

        #pragma unroll
        for (int ci = 0; ci < KC; ci++) {
            // broadcast-packed x window: rows tr,tr+1, cols [c0, c0+9)
            unsigned long long xd[2][9];
            #pragma unroll
            for (int s = 0; s < 2; s++)
                #pragma unroll
                for (int e = 0; e < 9; e++)
                    xd[s][e] = dup_f32(Xs[ci][tr + s][c0 + e]);

            #pragma unroll
            for (int t = 0; t < 4; t++) {
                const int dy = t >> 1, dx = t & 1;
                const unsigned long long* wrow =
                    reinterpret_cast<const unsigned long long*>(&Ws[ci][t][0]);
                unsigned long long wp4[4];
                #pragma unroll
                for (int cp = 0; cp < 4; cp++) wp4[cp] = wrow[tc * 4 + cp];
                #pragma unroll
                for (int cp = 0; cp < 4; cp++)
                    #pragma unroll
                    for (int j = 0; j < 8; j++)
                        asm("fma.rn.f32x2 %0, %1, %2, %0;"
                            : "+l"(acc2[cp][j])
                            : "l"(wp4[cp]), "l"(xd[1 - dy][j + 1 - dx]));
            }
        }
        __syncthreads();
    }

    // ---- epilogue: unpack, add bias, write strided output ----
    const int oy = 2 * (y0 + tr) + py;
    #pragma unroll
    for (int cp = 0; cp < 4; cp++) {
        int co = co0 + tc * 8 + cp * 2;
        float b0 = __ldg(&g_bias[co]);
        float b1 = __ldg(&g_bias[co + 1]);
        float* o0 = out + ((size_t)(b * COUT + co) * HOUT + oy) * HOUT;
        float* o1 = o0 + (size_t)HOUT * HOUT;
        #pragma unroll
        for (int j = 0; j < 8; j++) {
            unsigned lo = (unsigned)(acc2[cp][j] & 0xffffffffull);
            unsigned hi = (unsigned)(acc2[cp][j] >> 32);
            int ox = 2 * (x0 + c0 + j) + px;
            o0[ox] = __uint_as_float(lo) + b0;
            o1[ox] = __uint_as_float(hi) + b1;
        }
    }
}

// ---------------------------------------------------------------------------
extern "C" void kernel_launch(void* const* d_in, const int* in_sizes, int n_in,
                              void* d_out, int out_size)
{
    const float* x = (const float*)d_in[0];   // [8,512,64,64]
    const float* W = (const float*)d_in[1];   // [8,64,32,4,4]
    const float* b = (const float*)d_in[2];   // [8,32]
    float* out = (float*)d_out;               // [8,256,128,128]

    prep_w_kernel<<<(4 * 4 * CIN * COUT + 255) / 256, 256>>>(W);
    prep_b_kernel<<<1, 256>>>(b);

    dim3 grid(32, 2, 32);
    hconv_kernel<<<grid, 256>>>(x, out);
}

// round 7
// speedup vs baseline: 2.7605x; 2.7571x over previous
#include <cuda_runtime.h>
#include <cuda_bf16.h>
#include <cstdint>

// ---------------------------------------------------------------------------
// HyperTransposeConv via mma.sync bf16 split-precision (baseline PTX only —
// the harness front-end targets compute_103, which rejects tcgen05).
//   x[8,512,64,64] fp32, W[8,64,32,4,4], b[8,32] -> out[8,256,128,128]
//   stride=2, padding=1, K=4.
// Per (b,parity): out[pix, co] = sum_{tap, ci} x_shift[pix, ci] * Wbig[co, tap*512+ci]
// fp32 emulated as bf16 hi/lo: D += Ah*Bh + Al*Bh + Ah*Bl  (fp32 accum)
// ---------------------------------------------------------------------------

#define CIN   512
#define COUT  256
#define HIN   64
#define HOUT  128
#define BATCH 8

// Cayley-Dickson component table, get_comp_mat(8), row-major [i][j]
__device__ const int COMP[64] = {
    0,-1,-2,-1,-4,-3,-2,-3,
    1, 0,-3,-2,-5,-4,-1,-2,
    2, 1, 0,-1,-6,-5,-4,-3,
    3, 2, 1, 0,-7,-6,-5,-4,
    4, 3, 2, 3, 0,-1,-2,-1,
    5, 4, 1, 2, 1, 0,-3,-2,
    6, 5, 4, 3, 2, 1, 0,-1,
    7, 6, 5, 4, 3, 2, 1, 0};

// Scratch (device globals; no allocs allowed)
// xpad: [b][yp 66][xp 66][ci 512], zero halo, channels-last
__device__ __nv_bfloat16 g_xh[(size_t)BATCH * 66 * 66 * CIN];
__device__ __nv_bfloat16 g_xl[(size_t)BATCH * 66 * 66 * CIN];
// Wbig: [par 4][tap 4][co 256][ci 512]
__device__ __nv_bfloat16 g_wh[4 * 4 * COUT * CIN];
__device__ __nv_bfloat16 g_wl[4 * 4 * COUT * CIN];
__device__ float g_bias[COUT];

// ---------------------------------------------------------------------------
__device__ __forceinline__ uint32_t smem_u32(const void* p) {
    uint32_t a;
    asm("{ .reg .u64 t; cvta.to.shared.u64 t, %1; cvt.u32.u64 %0, t; }" : "=r"(a) : "l"(p));
    return a;
}

#define CP16(dst, src) \
    asm volatile("cp.async.cg.shared.global [%0], [%1], 16;" :: "r"(dst), "l"(src))
#define CP_COMMIT() asm volatile("cp.async.commit_group;" ::: "memory")
#define CP_WAIT1()  asm volatile("cp.async.wait_group 1;" ::: "memory")

#define LDSM4(r, a)                                                            \
    asm volatile("ldmatrix.sync.aligned.m8n8.x4.shared.b16 {%0,%1,%2,%3}, [%4];" \
        : "=r"((r)[0]), "=r"((r)[1]), "=r"((r)[2]), "=r"((r)[3]) : "r"(a))

#define MMA(d, A, B)                                                           \
    asm volatile("mma.sync.aligned.m16n8k16.row.col.f32.bf16.bf16.f32 "        \
        "{%0,%1,%2,%3}, {%4,%5,%6,%7}, {%8,%9}, {%0,%1,%2,%3};"                \
        : "+f"((d)[0]), "+f"((d)[1]), "+f"((d)[2]), "+f"((d)[3])               \
        : "r"((A)[0]), "r"((A)[1]), "r"((A)[2]), "r"((A)[3]),                  \
          "r"((B)[0]), "r"((B)[1]))

// ---------------------------------------------------------------------------
// prep_x: pad + transpose to channels-last, split fp32 -> bf16 hi/lo.
// grid (8 ci-chunks, 66 yp, 8 b), block 256
// ---------------------------------------------------------------------------
__global__ void prep_x_kernel(const float* __restrict__ x)
{
    __shared__ float tile[64][65];
    const int cc = blockIdx.x * 64;
    const int yp = blockIdx.y;
    const int b  = blockIdx.z;
    const int iy = yp - 1;
    const int tid = threadIdx.x;
    const int cr = tid >> 6, xq = tid & 63;

    if (iy >= 0 && iy < HIN) {
        #pragma unroll
        for (int i = 0; i < 16; i++) {
            int ci = cr + i * 4;
            tile[ci][xq] = x[((size_t)(b * CIN + cc + ci) * HIN + iy) * HIN + xq];
        }
    } else {
        #pragma unroll
        for (int i = 0; i < 16; i++) tile[cr + i * 4][xq] = 0.0f;
    }
    __syncthreads();

    for (int u = tid; u < 66 * 8; u += 256) {
        int xp = u >> 3, g = u & 7;
        int ix = xp - 1;
        __align__(16) __nv_bfloat16 hv[8], lv[8];
        #pragma unroll
        for (int k = 0; k < 8; k++) {
            float v = (ix >= 0 && ix < HIN) ? tile[g * 8 + k][ix] : 0.0f;
            __nv_bfloat16 h = __float2bfloat16(v);
            hv[k] = h;
            lv[k] = __float2bfloat16(v - __bfloat162float(h));
        }
        size_t o = ((size_t)(b * 66 + yp) * 66 + xp) * CIN + cc + g * 8;
        *(uint4*)(g_xh + o) = *(const uint4*)hv;
        *(uint4*)(g_xl + o) = *(const uint4*)lv;
    }
}

// ---------------------------------------------------------------------------
// prep_w: fused block weights [par][tap][co][ci], bf16 hi/lo split.
// ---------------------------------------------------------------------------
__global__ void prep_w_kernel(const float* __restrict__ W)
{
    int idx = blockIdx.x * blockDim.x + threadIdx.x;
    if (idx >= 4 * 4 * COUT * CIN) return;
    int ci  = idx & 511;
    int co  = (idx >> 9) & 255;
    int tap = (idx >> 17) & 3;
    int par = idx >> 19;

    int i = co >> 5, cop = co & 31;
    int j = ci >> 6, cj = ci & 63;
    int c = COMP[i * 8 + j];
    float sign = (c < 0) ? -1.0f : 1.0f;
    int widx = (c < 0) ? -c : c;

    int py = par >> 1, px = par & 1;
    int dy = tap >> 1, dx = tap & 1;
    int ky = 2 * dy + 1 - py;
    int kx = 2 * dx + 1 - px;

    float v = sign * W[(((widx * 64 + cj) * 32 + cop) * 4 + ky) * 4 + kx];
    __nv_bfloat16 h = __float2bfloat16(v);
    g_wh[idx] = h;
    g_wl[idx] = __float2bfloat16(v - __bfloat162float(h));
}

__global__ void prep_b_kernel(const float* __restrict__ b)
{
    int co = threadIdx.x;
    int i = co >> 5, cop = co & 31;
    float s = 0.0f;
    #pragma unroll
    for (int j = 0; j < 8; j++) {
        int c = COMP[i * 8 + j];
        float sign = (c < 0) ? -1.0f : 1.0f;
        int widx = (c < 0) ? -c : c;
        s += sign * b[widx * 32 + cop];
    }
    g_bias[co] = s;
}

// ---------------------------------------------------------------------------
// Main MMA kernel.
// Grid (2 ntile, 16 mtile, 32 = b*4+par), 256 threads (8 warps, 4x2 warp grid).
// Block tile: M=256 pixels (4 rows x 64 cols), N=128 co.
// K loop: 32 ci-chunks of 16; within each, 4 taps read shifted windows of one
// x-halo tile (5 rows x 65 cols) -> effective K = 64 per chunk.
//
// SMEM stage: A halo 2 planes x (5*65 rows of 48B)  = 31232 B
//             B       2 planes x (4*128 rows of 48B) = 49152 B  -> 80384 B
// Double buffered: 160768 B. Epilogue overlays [256][129] fp32 = 132096 B.
// Row stride 48B => ldmatrix granules (3c+s) mod 8 all distinct: conflict-free.
// ---------------------------------------------------------------------------
#define A_PL   15616                 // A plane stride (5*65*48 = 15600, pad)
#define B_SEC  31232
#define B_PL   24576                 // 4*128*48
#define STAGE  80384
#define NCH    32
#define SMEM_SZ 160768

extern __shared__ char smem[];

__device__ __forceinline__ void ldchunk(uint32_t sbase, int b, int y0p, int px,
                                        int par, int co0, int cc, int tid)
{
    // A halo: 5 rows x 65 cols x 16ci (2 x 16B granules) x 2 planes = 1300
    for (int u = tid; u < 1300; u += 256) {
        int pl  = u >= 650;
        int v   = pl ? u - 650 : u;
        int row = v / 130;
        int rem = v - row * 130;
        int col = rem >> 1;
        int slot = rem & 1;
        uint32_t dst = sbase + pl * A_PL + (row * 65 + col) * 48 + slot * 16;
        const __nv_bfloat16* src = (pl ? g_xl : g_xh)
            + ((size_t)(b * 66 + y0p + row) * 66 + px + col) * CIN + cc + slot * 8;
        CP16(dst, src);
    }
    // B: 4 taps x 128 co x 16ci x 2 planes = 2048 granules
    for (int u = tid; u < 2048; u += 256) {
        int pl  = u >= 1024;
        int v   = u & 1023;
        int tap = v >> 8;
        int r   = v & 255;
        int co  = r >> 1;
        int slot = r & 1;
        uint32_t dst = sbase + B_SEC + pl * B_PL + (tap * 128 + co) * 48 + slot * 16;
        const __nv_bfloat16* src = (pl ? g_wl : g_wh)
            + ((size_t)((par * 4 + tap) * COUT) + co0 + co) * CIN + cc + slot * 8;
        CP16(dst, src);
    }
}

__global__ void __launch_bounds__(256, 1)
hconv_mma_kernel(float* __restrict__ out)
{
    const int tid  = threadIdx.x;
    const int lane = tid & 31;
    const int wid  = tid >> 5;
    const int wm   = wid >> 1;          // 0..3 : pixel row of this warp
    const int wn   = wid & 1;           // 0..1 : 64-co half
    const int co0  = blockIdx.x * 128;
    const int y0   = blockIdx.y * 4;
    const int z    = blockIdx.z;
    const int b    = z >> 2;
    const int par  = z & 3;
    const int py   = par >> 1, px = par & 1;
    const uint32_t sb = smem_u32(smem);

    float acc[4][8][4];
    #pragma unroll
    for (int mt = 0; mt < 4; mt++)
        #pragma unroll
        for (int q = 0; q < 8; q++)
            #pragma unroll
            for (int r = 0; r < 4; r++) acc[mt][q][r] = 0.0f;

    // ldmatrix lane offsets (dy=dx=0 reference position)
    uint32_t aoff[4];
    #pragma unroll
    for (int mt = 0; mt < 4; mt++) {
        int c = mt * 16 + (lane & 15);
        aoff[mt] = ((wm + 1) * 65 + (c + 1)) * 48 + (lane >> 4) * 16;
    }
    const uint32_t boff = (wn * 64 + ((lane >> 4) & 1) * 8 + (lane & 7)) * 48
                        + ((lane >> 3) & 1) * 16;

    ldchunk(sb, b, y0 + py, px, par, co0, 0, tid);
    CP_COMMIT();

    #pragma unroll 1
    for (int ch = 0; ch < NCH; ch++) {
        const int s = ch & 1;
        if (ch + 1 < NCH)
            ldchunk(sb + (s ^ 1) * STAGE, b, y0 + py, px, par, co0,
                    (ch + 1) * 16, tid);
        CP_COMMIT();
        CP_WAIT1();
        __syncthreads();

        const uint32_t st = sb + s * STAGE;
        #pragma unroll
        for (int tap = 0; tap < 4; tap++) {
            const int dy = tap >> 1, dx = tap & 1;
            const uint32_t ash = st - dy * 3120 - dx * 48;   // 65*48 = 3120

            uint32_t Ah[4][4], Al[4][4];
            #pragma unroll
            for (int mt = 0; mt < 4; mt++) {
                LDSM4(Ah[mt], ash + aoff[mt]);
                LDSM4(Al[mt], ash + A_PL + aoff[mt]);
            }
            uint32_t Bh[8][2], Bl[8][2];
            const uint32_t bb = st + B_SEC + tap * 6144 + boff;  // 128*48=6144
            #pragma unroll
            for (int q2 = 0; q2 < 4; q2++) {
                uint32_t r4[4];
                LDSM4(r4, bb + q2 * 768);                         // 16*48=768
                Bh[2*q2][0] = r4[0]; Bh[2*q2][1] = r4[1];
                Bh[2*q2+1][0] = r4[2]; Bh[2*q2+1][1] = r4[3];
                LDSM4(r4, bb + B_PL + q2 * 768);
                Bl[2*q2][0] = r4[0]; Bl[2*q2][1] = r4[1];
                Bl[2*q2+1][0] = r4[2]; Bl[2*q2+1][1] = r4[3];
            }
            // term 0: Ah*Bh, term 1: Al*Bh, term 2: Ah*Bl
            #pragma unroll
            for (int mt = 0; mt < 4; mt++)
                #pragma unroll
                for (int q = 0; q < 8; q++) MMA(acc[mt][q], Ah[mt], Bh[q]);
            #pragma unroll
            for (int mt = 0; mt < 4; mt++)
                #pragma unroll
                for (int q = 0; q < 8; q++) MMA(acc[mt][q], Al[mt], Bh[q]);
            #pragma unroll
            for (int mt = 0; mt < 4; mt++)
                #pragma unroll
                for (int q = 0; q < 8; q++) MMA(acc[mt][q], Ah[mt], Bl[q]);
        }
        __syncthreads();
    }

    // ---- epilogue: acc -> smem [pix 256][co 129 padded] -> coalesced-ish gmem
    float* sp = (float*)smem;
    #pragma unroll
    for (int mt = 0; mt < 4; mt++) {
        const int cb = mt * 16 + (lane >> 2);
        const int p0 = wm * 64 + cb;
        #pragma unroll
        for (int q = 0; q < 8; q++) {
            const int co_l = wn * 64 + q * 8 + 2 * (lane & 3);
            sp[p0 * 129 + co_l]           = acc[mt][q][0];
            sp[p0 * 129 + co_l + 1]       = acc[mt][q][1];
            sp[(p0 + 8) * 129 + co_l]     = acc[mt][q][2];
            sp[(p0 + 8) * 129 + co_l + 1] = acc[mt][q][3];
        }
    }
    __syncthreads();

    #pragma unroll 1
    for (int it = 0; it < 64; it++) {
        const int u    = wid + it * 8;
        const int co_l = u >> 2;
        const int pr   = u & 3;
        const float bias = g_bias[co0 + co_l];
        const int oy = 2 * (y0 + pr) + py;
        float* orow = out + ((size_t)(b * COUT + co0 + co_l) * HOUT + oy) * HOUT;
        #pragma unroll
        for (int h = 0; h < 2; h++) {
            const int c = lane + h * 32;
            orow[2 * c + px] = sp[(pr * 64 + c) * 129 + co_l] + bias;
        }
    }
}

// ---------------------------------------------------------------------------
extern "C" void kernel_launch(void* const* d_in, const int* in_sizes, int n_in,
                              void* d_out, int out_size)
{
    const float* x = (const float*)d_in[0];   // [8,512,64,64]
    const float* W = (const float*)d_in[1];   // [8,64,32,4,4]
    const float* b = (const float*)d_in[2];   // [8,32]
    float* out = (float*)d_out;               // [8,256,128,128]

    prep_x_kernel<<<dim3(8, 66, 8), 256>>>(x);
    prep_w_kernel<<<(4 * 4 * COUT * CIN + 255) / 256, 256>>>(W);
    prep_b_kernel<<<1, 256>>>(b);

    cudaFuncSetAttribute(hconv_mma_kernel,
                         cudaFuncAttributeMaxDynamicSharedMemorySize, SMEM_SZ);
    hconv_mma_kernel<<<dim3(2, 16, 32), 256, SMEM_SZ>>>(out);
}